// round 13
// baseline (speedup 1.0000x reference)
#include <cuda_runtime.h>
#include <cuda_bf16.h>
#include <cstdint>

#define SQ 2048
#define DM 1024
#define NB 2
#define NH 16
#define DK 64
#define MI (1024L * 1024L)

// One big bf16 scratch buffer (allocation-free __device__ global), 144MB
__device__ __align__(256) __nv_bfloat16 g_buf[72 * MI];
// per-(z,row,colblock) partial sums of exp(logits): 32*2048*32 floats = 8MB
__device__ float g_ps[(long)NB * NH * SQ * 32];

#define O_INH (0 * MI)
#define O_INL (12 * MI)
#define O_WH  (24 * MI)
#define O_WL  (28 * MI)
#define O_QH  (32 * MI)
#define O_QL  (36 * MI)
#define O_KH  (40 * MI)
#define O_KL  (44 * MI)
#define O_VH  (48 * MI)
#define O_VL  (52 * MI)
#define O_VTH (56 * MI)
#define O_VTL (60 * MI)
#define O_CH  (64 * MI)
#define O_CL  (68 * MI)

__device__ __forceinline__ uint32_t smem_u32(const void* p) {
    uint32_t a;
    asm("{ .reg .u64 t; cvta.to.shared.u64 t, %1; cvt.u32.u64 %0, t; }" : "=r"(a) : "l"(p));
    return a;
}

#define LDSM4(r0, r1, r2, r3, addr) \
    asm volatile("ldmatrix.sync.aligned.m8n8.x4.shared.b16 {%0,%1,%2,%3}, [%4];" \
        : "=r"(r0), "=r"(r1), "=r"(r2), "=r"(r3) : "r"(addr))

#define MMA16816(d, a, b) \
    asm volatile("mma.sync.aligned.m16n8k16.row.col.f32.bf16.bf16.f32 " \
        "{%0,%1,%2,%3}, {%4,%5,%6,%7}, {%8,%9}, {%0,%1,%2,%3};" \
        : "+f"((d)[0]), "+f"((d)[1]), "+f"((d)[2]), "+f"((d)[3]) \
        : "r"((a)[0]), "r"((a)[1]), "r"((a)[2]), "r"((a)[3]), "r"((b)[0]), "r"((b)[1]))

#define CP16(dst, src) \
    asm volatile("cp.async.cg.shared.global [%0], [%1], 16;" :: "r"(dst), "l"(src))
#define CP_COMMIT() asm volatile("cp.async.commit_group;")
#define CP_WAIT(n)  asm volatile("cp.async.wait_group %0;" :: "n"(n))

// SW64 swizzle for 64-byte rows
#define SW64(off) ((off) ^ (((off) >> 3) & 0x30))

__device__ __forceinline__ void split2(float c0, float c1, uint32_t& hi, uint32_t& lo) {
    asm("cvt.rn.bf16x2.f32 %0, %1, %2;" : "=r"(hi) : "f"(c1), "f"(c0));
    float f0 = __uint_as_float(hi << 16);
    float f1 = __uint_as_float(hi & 0xffff0000u);
    asm("cvt.rn.bf16x2.f32 %0, %1, %2;" : "=r"(lo) : "f"(c1 - f1), "f"(c0 - f0));
}

// All 7 fp32->bf16 hi/lo splits in one launch; grid.x = 4096 covers the 1M-quad inputs,
// weight planes (256K quads) early-exit via the n4 guard.
__global__ __launch_bounds__(256) void split_all(
    const float* __restrict__ q, const float* __restrict__ k, const float* __restrict__ v,
    const float* __restrict__ wq, const float* __restrict__ wk,
    const float* __restrict__ wv, const float* __restrict__ wo)
{
    int z = blockIdx.y;
    const float* src;
    long oh, ol, n4;
    switch (z) {
        case 0: src = q;  oh = O_INH;          ol = O_INL;          n4 = MI; break;
        case 1: src = k;  oh = O_INH + 4 * MI; ol = O_INL + 4 * MI; n4 = MI; break;
        case 2: src = v;  oh = O_INH + 8 * MI; ol = O_INL + 8 * MI; n4 = MI; break;
        case 3: src = wq; oh = O_WH;           ol = O_WL;           n4 = MI / 4; break;
        case 4: src = wk; oh = O_WH + 1 * MI;  ol = O_WL + 1 * MI;  n4 = MI / 4; break;
        case 5: src = wv; oh = O_WH + 2 * MI;  ol = O_WL + 2 * MI;  n4 = MI / 4; break;
        default: src = wo; oh = O_WH + 3 * MI; ol = O_WL + 3 * MI;  n4 = MI / 4; break;
    }
    long i = (long)blockIdx.x * 256 + threadIdx.x;
    if (i >= n4) return;
    float4 val = ((const float4*)src)[i];
    uint32_t h01, h23, l01, l23;
    split2(val.x, val.y, h01, l01);
    split2(val.z, val.w, h23, l23);
    uint2 h; h.x = h01; h.y = h23;
    uint2 l; l.x = l01; l.y = l23;
    ((uint2*)(g_buf + oh))[i] = h;
    ((uint2*)(g_buf + ol))[i] = l;
}

__global__ __launch_bounds__(256) void transpose_hl() {
    __shared__ unsigned short t[32][34];
    int b = blockIdx.z;
    int d0 = blockIdx.x * 32, s0 = blockIdx.y * 32;
    int tx = threadIdx.x, ty = threadIdx.y;
#pragma unroll
    for (int a = 0; a < 2; a++) {
        const unsigned short* src = (const unsigned short*)(g_buf + (a ? O_VL : O_VH)) + (long)b * SQ * DM;
        unsigned short* dst = (unsigned short*)(g_buf + (a ? O_VTL : O_VTH)) + (long)b * DM * SQ;
#pragma unroll
        for (int i = 0; i < 32; i += 8)
            t[ty + i][tx] = src[(long)(s0 + ty + i) * DM + d0 + tx];
        __syncthreads();
#pragma unroll
        for (int i = 0; i < 32; i += 8)
            dst[(long)(d0 + ty + i) * SQ + s0 + tx] = t[tx][ty + i];
        __syncthreads();
    }
}

// ---------------- HMMA GEMM, bf16x3, cp.async double-buffered, KC=32, NTILE=64 ----------------
// Block 128 x 64, 8 warps in 4(M) x 2(N) grid, warp tile 32 x 32 (NG=4) -> 32 acc regs,
// 3 blocks/SM (6 warps/SMSP).
// MODE 0: normal GEMM.  MODE 1: PV with fused normalization.  MODE 2: QK with exp epilogue.
template<int MODE>
__global__ void __launch_bounds__(256, 3) mm_bf(
    long oAh, long oAl, int lda, long sAb, long sAh_,
    long oBh, long oBl, int ldb, long sBb, long sBh_,
    float* __restrict__ Cf, long oCh, long oCl, int ldc, long sCb, long sCh_,
    float* __restrict__ Alog, long sAlz,
    int K, float alpha, const float* __restrict__ bias,
    const float* __restrict__ bias2, const float* __restrict__ bias3, int H)
{
    extern __shared__ char smem[];
    constexpr int NTILE = 64;
    constexpr int ABYT = 128 * 32 * 2;       // 8KB
    constexpr int BBYT = NTILE * 32 * 2;     // 4KB
    constexpr int STAGE = 2 * ABYT + 2 * BBYT;
    constexpr int WN = NTILE / 2;            // 32
    constexpr int NG = WN / 8;               // 4

    uint32_t sb = smem_u32(smem);
    int tid = threadIdx.x, wid = tid >> 5, lane = tid & 31;
    int warp_m = wid & 3, warp_n = wid >> 2;
    int z = blockIdx.z, b = z / H, h = z - b * H;
    long m0 = (long)blockIdx.y * 128, n0 = (long)blockIdx.x * NTILE;

    if (H == 3) bias = (h == 0) ? bias : (h == 1 ? bias2 : bias3);

    const __nv_bfloat16* pAh = g_buf + oAh + (long)b * sAb + (long)h * sAh_;
    const __nv_bfloat16* pAl = g_buf + oAl + (long)b * sAb + (long)h * sAh_;
    const __nv_bfloat16* pBh = g_buf + oBh + (long)b * sBb + (long)h * sBh_;
    const __nv_bfloat16* pBl = g_buf + oBl + (long)b * sBb + (long)h * sBh_;

    float* smI = (float*)smem;
    float* Lz = nullptr;

    if (MODE == 1) {
        Lz = Alog + (long)z * sAlz;
        if (tid < 128) {
            const float* pp = g_ps + ((long)z * SQ + m0 + tid) * 32;
            float s = 0.f;
#pragma unroll
            for (int i = 0; i < 32; i++) s += pp[i];
            smI[tid] = 1.f / s;
        }
        __syncthreads();
    }

    // ---- per-thread load state ----
    const __nv_bfloat16 *aSrcH[2], *aSrcL[2];
    uint32_t aDst[2];
    if (MODE != 1) {
#pragma unroll
        for (int u = 0; u < 2; u++) {
            int unit = u * 256 + tid, row = unit >> 2, seg = unit & 3;
            long gi = (m0 + row) * (long)lda + seg * 8;
            aSrcH[u] = pAh + gi;
            aSrcL[u] = pAl + gi;
            uint32_t off = row * 64 + seg * 16;
            aDst[u] = sb + 1024 + SW64(off);
        }
    }
    const __nv_bfloat16 *bSrcH, *bSrcL;
    uint32_t bDst;
    {
        int row = tid >> 2, seg = tid & 3;
        long gi = (n0 + row) * (long)ldb + seg * 8;
        bSrcH = pBh + gi;
        bSrcL = pBl + gi;
        uint32_t off = row * 64 + seg * 16;
        bDst = sb + 1024 + 2 * ABYT + SW64(off);
    }
    // computeP state (MODE 1)
    float* eSrc[4];
    uint32_t pDst[4];
    float eIs[4];
    if (MODE == 1) {
#pragma unroll
        for (int u = 0; u < 4; u++) {
            int unit = u * 256 + tid, row = unit >> 3, c4 = (unit & 7) << 2;
            eSrc[u] = Lz + (m0 + row) * (long)SQ + c4;
            uint32_t off = row * 64 + (c4 << 1);
            pDst[u] = SW64(off);
            eIs[u] = smI[row];
        }
    }
    // LDSM addresses (stage 0; add stOff at use)
    int lrow = lane & 15, lcb = (lane >> 4) << 4;
    uint32_t aAd[2][2], bAd[2][NG / 2];
#pragma unroll
    for (int ks = 0; ks < 2; ks++) {
        int cb = ks * 32 + lcb;
#pragma unroll
        for (int im = 0; im < 2; im++) {
            int row = warp_m * 32 + im * 16 + lrow;
            uint32_t off = row * 64 + cb;
            aAd[ks][im] = sb + 1024 + SW64(off);
        }
#pragma unroll
        for (int g2 = 0; g2 < NG / 2; g2++) {
            int row = warp_n * WN + g2 * 16 + lrow;
            uint32_t off = row * 64 + cb;
            bAd[ks][g2] = sb + 1024 + 2 * ABYT + SW64(off);
        }
    }

    float acc[2][NG][4] = {};
    const int nc = K >> 5;

    // initial load: chunk 0 -> stage 0
    if (MODE != 1) {
#pragma unroll
        for (int u = 0; u < 2; u++) {
            CP16(aDst[u], aSrcH[u]);
            CP16(aDst[u] + ABYT, aSrcL[u]);
            aSrcH[u] += 32; aSrcL[u] += 32;
        }
    }
    CP16(bDst, bSrcH);
    CP16(bDst + BBYT, bSrcL);
    bSrcH += 32; bSrcL += 32;
    CP_COMMIT();
    if (MODE == 1) {
#pragma unroll
        for (int u = 0; u < 4; u++) {
            float4 e = *(const float4*)eSrc[u];
            float is = eIs[u];
            float4 p; p.x = e.x * is; p.y = e.y * is; p.z = e.z * is; p.w = e.w * is;
            *(float4*)eSrc[u] = p;
            uint32_t hi01, hi23, lo01, lo23;
            split2(p.x, p.y, hi01, lo01);
            split2(p.z, p.w, hi23, lo23);
            char* aB = smem + 1024;
            uint32_t sw = pDst[u];
            *(uint32_t*)(aB + sw) = hi01;        *(uint32_t*)(aB + sw + 4) = hi23;
            *(uint32_t*)(aB + ABYT + sw) = lo01; *(uint32_t*)(aB + ABYT + sw + 4) = lo23;
            eSrc[u] += 32;
        }
    }

    for (int c = 0; c < nc; c++) {
        uint32_t stOff = (uint32_t)(c & 1) * STAGE;
        uint32_t nxOff = (uint32_t)((c + 1) & 1) * STAGE;
        CP_WAIT(0);
        __syncthreads();
        if (c + 1 < nc) {
            if (MODE != 1) {
#pragma unroll
                for (int u = 0; u < 2; u++) {
                    CP16(aDst[u] + nxOff, aSrcH[u]);
                    CP16(aDst[u] + nxOff + ABYT, aSrcL[u]);
                    aSrcH[u] += 32; aSrcL[u] += 32;
                }
            }
            CP16(bDst + nxOff, bSrcH);
            CP16(bDst + nxOff + BBYT, bSrcL);
            bSrcH += 32; bSrcL += 32;
            CP_COMMIT();
        }

#pragma unroll
        for (int ks = 0; ks < 2; ks++) {
            uint32_t ah[2][4], al[2][4];
#pragma unroll
            for (int im = 0; im < 2; im++) {
                uint32_t ad = aAd[ks][im] + stOff;
                LDSM4(ah[im][0], ah[im][1], ah[im][2], ah[im][3], ad);
                LDSM4(al[im][0], al[im][1], al[im][2], al[im][3], ad + ABYT);
            }
#pragma unroll
            for (int g2 = 0; g2 < NG / 2; g2++) {
                uint32_t bd = bAd[ks][g2] + stOff;
                uint32_t bh[2][2], bl[2][2];
                uint32_t r0, r1, r2, r3;
                LDSM4(r0, r1, r2, r3, bd);
                bh[0][0] = r0; bh[0][1] = r2; bh[1][0] = r1; bh[1][1] = r3;
                LDSM4(r0, r1, r2, r3, bd + BBYT);
                bl[0][0] = r0; bl[0][1] = r2; bl[1][0] = r1; bl[1][1] = r3;
                // pass-major order: same-accumulator MMAs are 4 apart
#pragma unroll
                for (int im = 0; im < 2; im++)
#pragma unroll
                    for (int gg = 0; gg < 2; gg++)
                        MMA16816(acc[im][2 * g2 + gg], ah[im], bh[gg]);
#pragma unroll
                for (int im = 0; im < 2; im++)
#pragma unroll
                    for (int gg = 0; gg < 2; gg++)
                        MMA16816(acc[im][2 * g2 + gg], ah[im], bl[gg]);
#pragma unroll
                for (int im = 0; im < 2; im++)
#pragma unroll
                    for (int gg = 0; gg < 2; gg++)
                        MMA16816(acc[im][2 * g2 + gg], al[im], bh[gg]);
            }
        }
        if (MODE == 1 && c + 1 < nc) {
#pragma unroll
            for (int u = 0; u < 4; u++) {
                float4 e = *(const float4*)eSrc[u];
                float is = eIs[u];
                float4 p; p.x = e.x * is; p.y = e.y * is; p.z = e.z * is; p.w = e.w * is;
                *(float4*)eSrc[u] = p;
                uint32_t hi01, hi23, lo01, lo23;
                split2(p.x, p.y, hi01, lo01);
                split2(p.z, p.w, hi23, lo23);
                char* aB = smem + 1024 + nxOff;
                uint32_t sw = pDst[u];
                *(uint32_t*)(aB + sw) = hi01;        *(uint32_t*)(aB + sw + 4) = hi23;
                *(uint32_t*)(aB + ABYT + sw) = lo01; *(uint32_t*)(aB + ABYT + sw + 4) = lo23;
                eSrc[u] += 32;
            }
        }
    }

    // ---- epilogues ----
    if (MODE == 2) {
        float* pC = Cf + (long)b * sCb + (long)h * sCh_;
        float rs[2][2] = {};
#pragma unroll
        for (int im = 0; im < 2; im++) {
            long r0 = m0 + warp_m * 32 + im * 16 + (lane >> 2);
            float* p0 = pC + r0 * (long)ldc + n0 + warp_n * WN + (lane & 3) * 2;
            float* p1 = p0 + 8 * (long)ldc;
#pragma unroll
            for (int g = 0; g < NG; g++) {
                float e0 = __expf(acc[im][g][0] * alpha);
                float e1 = __expf(acc[im][g][1] * alpha);
                float e2 = __expf(acc[im][g][2] * alpha);
                float e3 = __expf(acc[im][g][3] * alpha);
                rs[im][0] += e0 + e1;
                rs[im][1] += e2 + e3;
                float2 o0; o0.x = e0; o0.y = e1;
                float2 o1; o1.x = e2; o1.y = e3;
                *(float2*)(p0 + g * 8) = o0;
                *(float2*)(p1 + g * 8) = o1;
            }
        }
        __syncthreads();
        float* red = (float*)smem;
#pragma unroll
        for (int im = 0; im < 2; im++)
#pragma unroll
            for (int j = 0; j < 2; j++) {
                float v = rs[im][j];
                v += __shfl_xor_sync(~0u, v, 1);
                v += __shfl_xor_sync(~0u, v, 2);
                if ((lane & 3) == 0)
                    red[warp_n * 128 + warp_m * 32 + im * 16 + j * 8 + (lane >> 2)] = v;
            }
        __syncthreads();
        if (tid < 128) {
            float ps = red[tid] + red[128 + tid];
            g_ps[((long)z * SQ + m0 + tid) * 32 + blockIdx.x] = ps;
        }
    } else if (Cf) {
        float* pC = Cf + (long)b * sCb + (long)h * sCh_;
#pragma unroll
        for (int im = 0; im < 2; im++) {
            long r0 = m0 + warp_m * 32 + im * 16 + (lane >> 2);
            long col0 = n0 + warp_n * WN + (lane & 3) * 2;
            float* p0 = pC + r0 * (long)ldc + col0;
            float* p1 = p0 + 8 * (long)ldc;
#pragma unroll
            for (int g = 0; g < NG; g++) {
                long col = col0 + g * 8;
                float bx = bias ? bias[col] : 0.f;
                float by = bias ? bias[col + 1] : 0.f;
                float2 o0, o1;
                o0.x = acc[im][g][0] * alpha + bx;
                o0.y = acc[im][g][1] * alpha + by;
                o1.x = acc[im][g][2] * alpha + bx;
                o1.y = acc[im][g][3] * alpha + by;
                *(float2*)(p0 + g * 8) = o0;
                *(float2*)(p1 + g * 8) = o1;
            }
        }
    } else {
        __nv_bfloat16* pCh = g_buf + oCh + (long)b * sCb + (long)h * sCh_;
        __nv_bfloat16* pCl = g_buf + oCl + (long)b * sCb + (long)h * sCh_;
#pragma unroll
        for (int im = 0; im < 2; im++) {
            long r0 = m0 + warp_m * 32 + im * 16 + (lane >> 2);
            long col0 = n0 + warp_n * WN + (lane & 3) * 2;
            __nv_bfloat16* h0 = pCh + r0 * (long)ldc + col0;
            __nv_bfloat16* l0 = pCl + r0 * (long)ldc + col0;
#pragma unroll
            for (int g = 0; g < NG; g++) {
                long col = col0 + g * 8;
                float bx = bias ? bias[col] : 0.f;
                float by = bias ? bias[col + 1] : 0.f;
                float c0 = acc[im][g][0] * alpha + bx;
                float c1 = acc[im][g][1] * alpha + by;
                float c2 = acc[im][g][2] * alpha + bx;
                float c3 = acc[im][g][3] * alpha + by;
                uint32_t hA, lA, hB, lB;
                split2(c0, c1, hA, lA);
                split2(c2, c3, hB, lB);
                *(uint32_t*)(h0 + g * 8) = hA;
                *(uint32_t*)(l0 + g * 8) = lA;
                *(uint32_t*)(h0 + 8 * (long)ldc + g * 8) = hB;
                *(uint32_t*)(l0 + 8 * (long)ldc + g * 8) = lB;
            }
        }
    }
}

extern "C" void kernel_launch(void* const* d_in, const int* in_sizes, int n_in,
                              void* d_out, int out_size) {
    const float* query = (const float*)d_in[0];
    const float* key   = (const float*)d_in[1];
    const float* value = (const float*)d_in[2];
    const float* Wq = (const float*)d_in[3];
    const float* bq = (const float*)d_in[4];
    const float* Wk = (const float*)d_in[5];
    const float* bk = (const float*)d_in[6];
    const float* Wv = (const float*)d_in[7];
    const float* bv = (const float*)d_in[8];
    const float* Wo = (const float*)d_in[9];
    const float* bo = (const float*)d_in[10];

    float* out = (float*)d_out;
    float* scores = out + (long)NB * SQ * DM;

    split_all<<<dim3(4096, 7), 256>>>(query, key, value, Wq, Wk, Wv, Wo);

    const int SM_SZ = 1024 + 2 * (2 * 128 * 32 * 2 + 2 * 64 * 32 * 2);   // 50176
    cudaFuncSetAttribute(mm_bf<0>, cudaFuncAttributeMaxDynamicSharedMemorySize, SM_SZ);
    cudaFuncSetAttribute(mm_bf<2>, cudaFuncAttributeMaxDynamicSharedMemorySize, SM_SZ);
    cudaFuncSetAttribute(mm_bf<1>, cudaFuncAttributeMaxDynamicSharedMemorySize, SM_SZ);

    // merged Q/K/V projections (z = 0,1,2)
    dim3 gqkv(16, 32, 3);
    mm_bf<0><<<gqkv, 256, SM_SZ>>>(
        O_INH, O_INL, DM, 0, 4 * MI,
        O_WH, O_WL, DM, 0, 1 * MI,
        nullptr, O_QH, O_QL, DM, 0, 8 * MI,
        nullptr, 0, DM, 1.f, bq, bk, bv, 3);

    transpose_hl<<<dim3(DM / 32, SQ / 32, NB), dim3(32, 8)>>>();

    // QK^T: exp epilogue + 32 partial sums per row
    dim3 gqk(32, 16, NB * NH);
    mm_bf<2><<<gqk, 256, SM_SZ>>>(
        O_QH, O_QL, DM, (long)SQ * DM, DK, O_KH, O_KL, DM, (long)SQ * DM, DK,
        scores, 0, 0, SQ, (long)NH * SQ * SQ, (long)SQ * SQ,
        nullptr, 0, DK, 0.125f, nullptr, nullptr, nullptr, NH);

    // PV with fused normalization; P written back into scores
    dim3 gpv(1, 16, NB * NH);
    mm_bf<1><<<gpv, 256, SM_SZ>>>(
        0, 0, SQ, 0, 0, O_VTH, O_VTL, SQ, (long)DM * SQ, (long)DK * SQ,
        nullptr, O_CH, O_CL, DM, (long)SQ * DM, DK,
        scores, (long)SQ * SQ, SQ, 1.f, nullptr, nullptr, nullptr, NH);

    // out = ctx @ Wo^T + bo
    dim3 gproj(16, 32, 1);
    mm_bf<0><<<gproj, 256, SM_SZ>>>(
        O_CH, O_CL, DM, 0, 0, O_WH + 3 * MI, O_WL + 3 * MI, DM, 0, 0,
        out, 0, 0, DM, 0, 0, nullptr, 0, DM, 1.f, bo, nullptr, nullptr, 1);
}

// round 16
// speedup vs baseline: 1.0700x; 1.0700x over previous
#include <cuda_runtime.h>
#include <cuda_bf16.h>
#include <cstdint>

#define SQ 2048
#define DM 1024
#define NB 2
#define NH 16
#define DK 64
#define MI (1024L * 1024L)
#define NT 4

// One big bf16 scratch buffer (allocation-free __device__ global), 144MB
__device__ __align__(256) __nv_bfloat16 g_buf[72 * MI];
// per-(z,row,colblock) partial sums of exp(logits): 32*2048*16 floats = 4MB
__device__ float g_ps[(long)NB * NH * SQ * 16];

#define O_INH (0 * MI)
#define O_INL (12 * MI)
#define O_WH  (24 * MI)
#define O_WL  (28 * MI)
#define O_QH  (32 * MI)
#define O_QL  (36 * MI)
#define O_KH  (40 * MI)
#define O_KL  (44 * MI)
#define O_VH  (48 * MI)
#define O_VL  (52 * MI)
#define O_VTH (56 * MI)
#define O_VTL (60 * MI)
#define O_CH  (64 * MI)
#define O_CL  (68 * MI)

__device__ __forceinline__ uint32_t smem_u32(const void* p) {
    uint32_t a;
    asm("{ .reg .u64 t; cvta.to.shared.u64 t, %1; cvt.u32.u64 %0, t; }" : "=r"(a) : "l"(p));
    return a;
}

#define LDSM4(r0, r1, r2, r3, addr) \
    asm volatile("ldmatrix.sync.aligned.m8n8.x4.shared.b16 {%0,%1,%2,%3}, [%4];" \
        : "=r"(r0), "=r"(r1), "=r"(r2), "=r"(r3) : "r"(addr))

#define MMA16816(d, a, b) \
    asm volatile("mma.sync.aligned.m16n8k16.row.col.f32.bf16.bf16.f32 " \
        "{%0,%1,%2,%3}, {%4,%5,%6,%7}, {%8,%9}, {%0,%1,%2,%3};" \
        : "+f"((d)[0]), "+f"((d)[1]), "+f"((d)[2]), "+f"((d)[3]) \
        : "r"((a)[0]), "r"((a)[1]), "r"((a)[2]), "r"((a)[3]), "r"((b)[0]), "r"((b)[1]))

#define CP16(dst, src) \
    asm volatile("cp.async.cg.shared.global [%0], [%1], 16;" :: "r"(dst), "l"(src))
#define CP_COMMIT() asm volatile("cp.async.commit_group;")
#define CP_WAIT(n)  asm volatile("cp.async.wait_group %0;" :: "n"(n))

// SW64 swizzle (64B rows); SW128 (128B rows)
#define SW64(off)  ((off) ^ (((off) >> 3) & 0x30))
#define SW128(off) ((off) ^ (((off) >> 3) & 0x70))

__device__ __forceinline__ void split2(float c0, float c1, uint32_t& hi, uint32_t& lo) {
    asm("cvt.rn.bf16x2.f32 %0, %1, %2;" : "=r"(hi) : "f"(c1), "f"(c0));
    float f0 = __uint_as_float(hi << 16);
    float f1 = __uint_as_float(hi & 0xffff0000u);
    asm("cvt.rn.bf16x2.f32 %0, %1, %2;" : "=r"(lo) : "f"(c1 - f1), "f"(c0 - f0));
}

__device__ __forceinline__ void cvt_store64(char* base, int offHi, int offLo, int row, int c4, float4 v) {
    uint32_t hi01, hi23, lo01, lo23;
    split2(v.x, v.y, hi01, lo01);
    split2(v.z, v.w, hi23, lo23);
    uint32_t off = row * 64 + (c4 << 1);
    uint32_t sw = SW64(off);
    *(uint32_t*)(base + offHi + sw)     = hi01;
    *(uint32_t*)(base + offHi + sw + 4) = hi23;
    *(uint32_t*)(base + offLo + sw)     = lo01;
    *(uint32_t*)(base + offLo + sw + 4) = lo23;
}

// All 7 fp32->bf16 hi/lo splits in one launch
__global__ __launch_bounds__(256) void split_all(
    const float* __restrict__ q, const float* __restrict__ k, const float* __restrict__ v,
    const float* __restrict__ wq, const float* __restrict__ wk,
    const float* __restrict__ wv, const float* __restrict__ wo)
{
    int z = blockIdx.y;
    const float* src;
    long oh, ol, n4;
    switch (z) {
        case 0: src = q;  oh = O_INH;          ol = O_INL;          n4 = MI; break;
        case 1: src = k;  oh = O_INH + 4 * MI; ol = O_INL + 4 * MI; n4 = MI; break;
        case 2: src = v;  oh = O_INH + 8 * MI; ol = O_INL + 8 * MI; n4 = MI; break;
        case 3: src = wq; oh = O_WH;           ol = O_WL;           n4 = MI / 4; break;
        case 4: src = wk; oh = O_WH + 1 * MI;  ol = O_WL + 1 * MI;  n4 = MI / 4; break;
        case 5: src = wv; oh = O_WH + 2 * MI;  ol = O_WL + 2 * MI;  n4 = MI / 4; break;
        default: src = wo; oh = O_WH + 3 * MI; ol = O_WL + 3 * MI;  n4 = MI / 4; break;
    }
    long i = (long)blockIdx.x * 256 + threadIdx.x;
    if (i >= n4) return;
    float4 val = ((const float4*)src)[i];
    uint32_t h01, h23, l01, l23;
    split2(val.x, val.y, h01, l01);
    split2(val.z, val.w, h23, l23);
    uint2 h; h.x = h01; h.y = h23;
    uint2 l; l.x = l01; l.y = l23;
    ((uint2*)(g_buf + oh))[i] = h;
    ((uint2*)(g_buf + ol))[i] = l;
}

__global__ __launch_bounds__(256) void transpose_hl() {
    __shared__ unsigned short t[32][34];
    int b = blockIdx.z;
    int d0 = blockIdx.x * 32, s0 = blockIdx.y * 32;
    int tx = threadIdx.x, ty = threadIdx.y;
#pragma unroll
    for (int a = 0; a < 2; a++) {
        const unsigned short* src = (const unsigned short*)(g_buf + (a ? O_VL : O_VH)) + (long)b * SQ * DM;
        unsigned short* dst = (unsigned short*)(g_buf + (a ? O_VTL : O_VTH)) + (long)b * DM * SQ;
#pragma unroll
        for (int i = 0; i < 32; i += 8)
            t[ty + i][tx] = src[(long)(s0 + ty + i) * DM + d0 + tx];
        __syncthreads();
#pragma unroll
        for (int i = 0; i < 32; i += 8)
            dst[(long)(d0 + ty + i) * SQ + s0 + tx] = t[tx][ty + i];
        __syncthreads();
    }
}

// ---------------- Dedicated QK kernel: KC=64 (full K), A loaded once, NT B-tiles ----------------
// Block computes 128 x (NT*128) of exp(q@k^T / 8), writing exp values + per-colblock row sums.
// 8 warps 4(M) x 2(N), bf16x3, SW128 rows (64 bf16 = 128B).
__global__ void __launch_bounds__(256, 2) qk64(float* __restrict__ scores) {
    extern __shared__ char smem[];
    constexpr int ABYT = 128 * 64 * 2;   // 16KB per plane
    constexpr int BST = 2 * ABYT;        // B stage (hi+lo) = 32KB
    uint32_t sb = smem_u32(smem);
    int tid = threadIdx.x, wid = tid >> 5, lane = tid & 31;
    int warp_m = wid & 3, warp_n = wid >> 2;
    int z = blockIdx.z, b = z >> 4, h = z & 15;
    long m0 = (long)blockIdx.y * 128;

    const __nv_bfloat16* pAh = g_buf + O_QH + (long)b * SQ * DM + h * DK;
    const __nv_bfloat16* pAl = g_buf + O_QL + (long)b * SQ * DM + h * DK;
    const __nv_bfloat16* pBh = g_buf + O_KH + (long)b * SQ * DM + h * DK;
    const __nv_bfloat16* pBl = g_buf + O_KL + (long)b * SQ * DM + h * DK;
    float* pSc = scores + (long)z * SQ * SQ;

    const uint32_t aBase = sb + 1024;
    const uint32_t bBase = sb + 1024 + 2 * ABYT;

    // load A (q) hi+lo once: 128 rows x 128B
#pragma unroll
    for (int u = 0; u < 4; u++) {
        int unit = u * 256 + tid, row = unit >> 3, seg = unit & 7;
        long gi = (m0 + row) * (long)DM + seg * 8;
        uint32_t off = row * 128 + seg * 16;
        uint32_t d = aBase + SW128(off);
        CP16(d, pAh + gi);
        CP16(d + ABYT, pAl + gi);
    }
    // load B tile 0 -> stage 0
    {
        long n0t = (long)blockIdx.x * NT * 128;
#pragma unroll
        for (int u = 0; u < 4; u++) {
            int unit = u * 256 + tid, row = unit >> 3, seg = unit & 7;
            long gi = (n0t + row) * (long)DM + seg * 8;
            uint32_t off = row * 128 + seg * 16;
            uint32_t d = bBase + SW128(off);
            CP16(d, pBh + gi);
            CP16(d + ABYT, pBl + gi);
        }
    }
    CP_COMMIT();

    int lrow = lane & 15, lcb = (lane >> 4) << 4;

    for (int nt = 0; nt < NT; nt++) {
        uint32_t bSt = bBase + (uint32_t)(nt & 1) * BST;
        CP_WAIT(0);
        __syncthreads();
        if (nt + 1 < NT) {
            long n0t = ((long)blockIdx.x * NT + nt + 1) * 128;
            uint32_t bNx = bBase + (uint32_t)((nt + 1) & 1) * BST;
#pragma unroll
            for (int u = 0; u < 4; u++) {
                int unit = u * 256 + tid, row = unit >> 3, seg = unit & 7;
                long gi = (n0t + row) * (long)DM + seg * 8;
                uint32_t off = row * 128 + seg * 16;
                uint32_t d = bNx + SW128(off);
                CP16(d, pBh + gi);
                CP16(d + ABYT, pBl + gi);
            }
            CP_COMMIT();
        }

        float acc[2][8][4] = {};
#pragma unroll
        for (int ks = 0; ks < 4; ks++) {
            int cb = ks * 32 + lcb;
            uint32_t ah[2][4], al[2][4];
#pragma unroll
            for (int im = 0; im < 2; im++) {
                int row = warp_m * 32 + im * 16 + lrow;
                uint32_t off = row * 128 + cb;
                uint32_t ad = aBase + SW128(off);
                LDSM4(ah[im][0], ah[im][1], ah[im][2], ah[im][3], ad);
                LDSM4(al[im][0], al[im][1], al[im][2], al[im][3], ad + ABYT);
            }
#pragma unroll
            for (int g2 = 0; g2 < 4; g2++) {
                int row = warp_n * 64 + g2 * 16 + lrow;
                uint32_t off = row * 128 + cb;
                uint32_t bd = bSt + SW128(off);
                uint32_t bh[2][2], bl[2][2];
                uint32_t r0, r1, r2, r3;
                LDSM4(r0, r1, r2, r3, bd);
                bh[0][0] = r0; bh[0][1] = r2; bh[1][0] = r1; bh[1][1] = r3;
                LDSM4(r0, r1, r2, r3, bd + ABYT);
                bl[0][0] = r0; bl[0][1] = r2; bl[1][0] = r1; bl[1][1] = r3;
#pragma unroll
                for (int im = 0; im < 2; im++)
#pragma unroll
                    for (int gg = 0; gg < 2; gg++)
                        MMA16816(acc[im][2 * g2 + gg], ah[im], bh[gg]);
#pragma unroll
                for (int im = 0; im < 2; im++)
#pragma unroll
                    for (int gg = 0; gg < 2; gg++)
                        MMA16816(acc[im][2 * g2 + gg], ah[im], bl[gg]);
#pragma unroll
                for (int im = 0; im < 2; im++)
#pragma unroll
                    for (int gg = 0; gg < 2; gg++)
                        MMA16816(acc[im][2 * g2 + gg], al[im], bh[gg]);
            }
        }

        // epilogue for this n-tile: exp, store, partial row sums
        long n0 = ((long)blockIdx.x * NT + nt) * 128;
        float rs[2][2] = {};
#pragma unroll
        for (int im = 0; im < 2; im++) {
            long r0 = m0 + warp_m * 32 + im * 16 + (lane >> 2);
            float* p0 = pSc + r0 * (long)SQ + n0 + warp_n * 64 + (lane & 3) * 2;
            float* p1 = p0 + 8 * (long)SQ;
#pragma unroll
            for (int g = 0; g < 8; g++) {
                float e0 = __expf(acc[im][g][0] * 0.125f);
                float e1 = __expf(acc[im][g][1] * 0.125f);
                float e2 = __expf(acc[im][g][2] * 0.125f);
                float e3 = __expf(acc[im][g][3] * 0.125f);
                rs[im][0] += e0 + e1;
                rs[im][1] += e2 + e3;
                float2 o0; o0.x = e0; o0.y = e1;
                float2 o1; o1.x = e2; o1.y = e3;
                *(float2*)(p0 + g * 8) = o0;
                *(float2*)(p1 + g * 8) = o1;
            }
        }
        __syncthreads();
        float* red = (float*)smem;   // [2][128], below tile region
#pragma unroll
        for (int im = 0; im < 2; im++)
#pragma unroll
            for (int j = 0; j < 2; j++) {
                float v = rs[im][j];
                v += __shfl_xor_sync(~0u, v, 1);
                v += __shfl_xor_sync(~0u, v, 2);
                if ((lane & 3) == 0)
                    red[warp_n * 128 + warp_m * 32 + im * 16 + j * 8 + (lane >> 2)] = v;
            }
        __syncthreads();
        if (tid < 128) {
            float ps = red[tid] + red[128 + tid];
            g_ps[((long)z * SQ + m0 + tid) * 16 + blockIdx.x * NT + nt] = ps;
        }
    }
}

// ---------------- HMMA GEMM, bf16x3, cp.async double-buffered, KC=32 (R9 proven) ----------------
// MODE 0: normal GEMM.  MODE 1: PV with fused normalization.
template<int NTILE, int MODE, int MINB>
__global__ void __launch_bounds__(256, MINB) mm_bf(
    long oAh, long oAl, int lda, long sAb, long sAh_,
    long oBh, long oBl, int ldb, long sBb, long sBh_,
    float* __restrict__ Cf, long oCh, long oCl, int ldc, long sCb, long sCh_,
    float* __restrict__ Alog, long sAlz,
    int K, float alpha, const float* __restrict__ bias,
    const float* __restrict__ bias2, const float* __restrict__ bias3, int H)
{
    extern __shared__ char smem[];
    constexpr int ABYT = 128 * 32 * 2;
    constexpr int BBYT = NTILE * 32 * 2;
    constexpr int STAGE = 2 * ABYT + 2 * BBYT;
    constexpr int WN = NTILE / 2;
    constexpr int NG = WN / 8;
    constexpr int BU = NTILE / 64;

    uint32_t sb = smem_u32(smem);
    int tid = threadIdx.x, wid = tid >> 5, lane = tid & 31;
    int warp_m = wid & 3, warp_n = wid >> 2;
    int z = blockIdx.z, b = z / H, h = z - b * H;
    long m0 = (long)blockIdx.y * 128, n0 = (long)blockIdx.x * NTILE;

    if (H == 3) bias = (h == 0) ? bias : (h == 1 ? bias2 : bias3);

    const __nv_bfloat16* pAh = g_buf + oAh + (long)b * sAb + (long)h * sAh_;
    const __nv_bfloat16* pAl = g_buf + oAl + (long)b * sAb + (long)h * sAh_;
    const __nv_bfloat16* pBh = g_buf + oBh + (long)b * sBb + (long)h * sBh_;
    const __nv_bfloat16* pBl = g_buf + oBl + (long)b * sBb + (long)h * sBh_;

    float* smI = (float*)smem;
    float* Lz = nullptr;

    if (MODE == 1) {
        Lz = Alog + (long)z * sAlz;
        if (tid < 128) {
            const float* pp = g_ps + ((long)z * SQ + m0 + tid) * 16;
            float s = 0.f;
#pragma unroll
            for (int i = 0; i < 16; i++) s += pp[i];
            smI[tid] = 1.f / s;
        }
        __syncthreads();
    }

    const __nv_bfloat16 *aSrcH[2], *aSrcL[2];
    uint32_t aDst[2];
    if (MODE != 1) {
#pragma unroll
        for (int u = 0; u < 2; u++) {
            int unit = u * 256 + tid, row = unit >> 2, seg = unit & 3;
            long gi = (m0 + row) * (long)lda + seg * 8;
            aSrcH[u] = pAh + gi;
            aSrcL[u] = pAl + gi;
            uint32_t off = row * 64 + seg * 16;
            aDst[u] = sb + 1024 + SW64(off);
        }
    }
    const __nv_bfloat16 *bSrcH[BU], *bSrcL[BU];
    uint32_t bDst[BU];
#pragma unroll
    for (int u = 0; u < BU; u++) {
        int unit = u * 256 + tid, row = unit >> 2, seg = unit & 3;
        long gi = (n0 + row) * (long)ldb + seg * 8;
        bSrcH[u] = pBh + gi;
        bSrcL[u] = pBl + gi;
        uint32_t off = row * 64 + seg * 16;
        bDst[u] = sb + 1024 + 2 * ABYT + SW64(off);
    }
    float* eSrc[4];
    uint32_t pDst[4];
    float eIs[4];
    if (MODE == 1) {
#pragma unroll
        for (int u = 0; u < 4; u++) {
            int unit = u * 256 + tid, row = unit >> 3, c4 = (unit & 7) << 2;
            eSrc[u] = Lz + (m0 + row) * (long)SQ + c4;
            uint32_t off = row * 64 + (c4 << 1);
            pDst[u] = SW64(off);
            eIs[u] = smI[row];
        }
    }
    int lrow = lane & 15, lcb = (lane >> 4) << 4;
    uint32_t aAd[2][2], bAd[2][NG / 2];
#pragma unroll
    for (int ks = 0; ks < 2; ks++) {
        int cb = ks * 32 + lcb;
#pragma unroll
        for (int im = 0; im < 2; im++) {
            int row = warp_m * 32 + im * 16 + lrow;
            uint32_t off = row * 64 + cb;
            aAd[ks][im] = sb + 1024 + SW64(off);
        }
#pragma unroll
        for (int g2 = 0; g2 < NG / 2; g2++) {
            int row = warp_n * WN + g2 * 16 + lrow;
            uint32_t off = row * 64 + cb;
            bAd[ks][g2] = sb + 1024 + 2 * ABYT + SW64(off);
        }
    }

    float acc[2][NG][4] = {};
    const int nc = K >> 5;

    if (MODE != 1) {
#pragma unroll
        for (int u = 0; u < 2; u++) {
            CP16(aDst[u], aSrcH[u]);
            CP16(aDst[u] + ABYT, aSrcL[u]);
            aSrcH[u] += 32; aSrcL[u] += 32;
        }
    }
#pragma unroll
    for (int u = 0; u < BU; u++) {
        CP16(bDst[u], bSrcH[u]);
        CP16(bDst[u] + BBYT, bSrcL[u]);
        bSrcH[u] += 32; bSrcL[u] += 32;
    }
    CP_COMMIT();
    if (MODE == 1) {
#pragma unroll
        for (int u = 0; u < 4; u++) {
            float4 e = *(const float4*)eSrc[u];
            float is = eIs[u];
            float4 p; p.x = e.x * is; p.y = e.y * is; p.z = e.z * is; p.w = e.w * is;
            *(float4*)eSrc[u] = p;
            uint32_t hi01, hi23, lo01, lo23;
            split2(p.x, p.y, hi01, lo01);
            split2(p.z, p.w, hi23, lo23);
            char* aB = smem + 1024;
            uint32_t sw = pDst[u];
            *(uint32_t*)(aB + sw) = hi01;        *(uint32_t*)(aB + sw + 4) = hi23;
            *(uint32_t*)(aB + ABYT + sw) = lo01; *(uint32_t*)(aB + ABYT + sw + 4) = lo23;
            eSrc[u] += 32;
        }
    }

    for (int c = 0; c < nc; c++) {
        uint32_t stOff = (uint32_t)(c & 1) * STAGE;
        uint32_t nxOff = (uint32_t)((c + 1) & 1) * STAGE;
        CP_WAIT(0);
        __syncthreads();
        if (c + 1 < nc) {
            if (MODE != 1) {
#pragma unroll
                for (int u = 0; u < 2; u++) {
                    CP16(aDst[u] + nxOff, aSrcH[u]);
                    CP16(aDst[u] + nxOff + ABYT, aSrcL[u]);
                    aSrcH[u] += 32; aSrcL[u] += 32;
                }
            }
#pragma unroll
            for (int u = 0; u < BU; u++) {
                CP16(bDst[u] + nxOff, bSrcH[u]);
                CP16(bDst[u] + nxOff + BBYT, bSrcL[u]);
                bSrcH[u] += 32; bSrcL[u] += 32;
            }
            CP_COMMIT();
        }

#pragma unroll
        for (int ks = 0; ks < 2; ks++) {
            uint32_t ah[2][4], al[2][4];
#pragma unroll
            for (int im = 0; im < 2; im++) {
                uint32_t ad = aAd[ks][im] + stOff;
                LDSM4(ah[im][0], ah[im][1], ah[im][2], ah[im][3], ad);
                LDSM4(al[im][0], al[im][1], al[im][2], al[im][3], ad + ABYT);
            }
#pragma unroll
            for (int g2 = 0; g2 < NG / 2; g2++) {
                uint32_t bd = bAd[ks][g2] + stOff;
                uint32_t bh[2][2], bl[2][2];
                uint32_t r0, r1, r2, r3;
                LDSM4(r0, r1, r2, r3, bd);
                bh[0][0] = r0; bh[0][1] = r2; bh[1][0] = r1; bh[1][1] = r3;
                LDSM4(r0, r1, r2, r3, bd + BBYT);
                bl[0][0] = r0; bl[0][1] = r2; bl[1][0] = r1; bl[1][1] = r3;
#pragma unroll
                for (int im = 0; im < 2; im++)
#pragma unroll
                    for (int gg = 0; gg < 2; gg++)
                        MMA16816(acc[im][2 * g2 + gg], ah[im], bh[gg]);
#pragma unroll
                for (int im = 0; im < 2; im++)
#pragma unroll
                    for (int gg = 0; gg < 2; gg++)
                        MMA16816(acc[im][2 * g2 + gg], ah[im], bl[gg]);
#pragma unroll
                for (int im = 0; im < 2; im++)
#pragma unroll
                    for (int gg = 0; gg < 2; gg++)
                        MMA16816(acc[im][2 * g2 + gg], al[im], bh[gg]);
            }
        }
        if (MODE == 1 && c + 1 < nc) {
#pragma unroll
            for (int u = 0; u < 4; u++) {
                float4 e = *(const float4*)eSrc[u];
                float is = eIs[u];
                float4 p; p.x = e.x * is; p.y = e.y * is; p.z = e.z * is; p.w = e.w * is;
                *(float4*)eSrc[u] = p;
                uint32_t hi01, hi23, lo01, lo23;
                split2(p.x, p.y, hi01, lo01);
                split2(p.z, p.w, hi23, lo23);
                char* aB = smem + 1024 + nxOff;
                uint32_t sw = pDst[u];
                *(uint32_t*)(aB + sw) = hi01;        *(uint32_t*)(aB + sw + 4) = hi23;
                *(uint32_t*)(aB + ABYT + sw) = lo01; *(uint32_t*)(aB + ABYT + sw + 4) = lo23;
                eSrc[u] += 32;
            }
        }
    }

    // ---- epilogues ----
    if (Cf) {
        float* pC = Cf + (long)b * sCb + (long)h * sCh_;
#pragma unroll
        for (int im = 0; im < 2; im++) {
            long r0 = m0 + warp_m * 32 + im * 16 + (lane >> 2);
            long col0 = n0 + warp_n * WN + (lane & 3) * 2;
            float* p0 = pC + r0 * (long)ldc + col0;
            float* p1 = p0 + 8 * (long)ldc;
#pragma unroll
            for (int g = 0; g < NG; g++) {
                long col = col0 + g * 8;
                float bx = bias ? bias[col] : 0.f;
                float by = bias ? bias[col + 1] : 0.f;
                float2 o0, o1;
                o0.x = acc[im][g][0] * alpha + bx;
                o0.y = acc[im][g][1] * alpha + by;
                o1.x = acc[im][g][2] * alpha + bx;
                o1.y = acc[im][g][3] * alpha + by;
                *(float2*)(p0 + g * 8) = o0;
                *(float2*)(p1 + g * 8) = o1;
            }
        }
    } else {
        __nv_bfloat16* pCh = g_buf + oCh + (long)b * sCb + (long)h * sCh_;
        __nv_bfloat16* pCl = g_buf + oCl + (long)b * sCb + (long)h * sCh_;
#pragma unroll
        for (int im = 0; im < 2; im++) {
            long r0 = m0 + warp_m * 32 + im * 16 + (lane >> 2);
            long col0 = n0 + warp_n * WN + (lane & 3) * 2;
            __nv_bfloat16* h0 = pCh + r0 * (long)ldc + col0;
            __nv_bfloat16* l0 = pCl + r0 * (long)ldc + col0;
#pragma unroll
            for (int g = 0; g < NG; g++) {
                long col = col0 + g * 8;
                float bx = bias ? bias[col] : 0.f;
                float by = bias ? bias[col + 1] : 0.f;
                float c0 = acc[im][g][0] * alpha + bx;
                float c1 = acc[im][g][1] * alpha + by;
                float c2 = acc[im][g][2] * alpha + bx;
                float c3 = acc[im][g][3] * alpha + by;
                uint32_t hA, lA, hB, lB;
                split2(c0, c1, hA, lA);
                split2(c2, c3, hB, lB);
                *(uint32_t*)(h0 + g * 8) = hA;
                *(uint32_t*)(l0 + g * 8) = lA;
                *(uint32_t*)(h0 + 8 * (long)ldc + g * 8) = hB;
                *(uint32_t*)(l0 + 8 * (long)ldc + g * 8) = lB;
            }
        }
    }
}

extern "C" void kernel_launch(void* const* d_in, const int* in_sizes, int n_in,
                              void* d_out, int out_size) {
    const float* query = (const float*)d_in[0];
    const float* key   = (const float*)d_in[1];
    const float* value = (const float*)d_in[2];
    const float* Wq = (const float*)d_in[3];
    const float* bq = (const float*)d_in[4];
    const float* Wk = (const float*)d_in[5];
    const float* bk = (const float*)d_in[6];
    const float* Wv = (const float*)d_in[7];
    const float* bv = (const float*)d_in[8];
    const float* Wo = (const float*)d_in[9];
    const float* bo = (const float*)d_in[10];

    float* out = (float*)d_out;
    float* scores = out + (long)NB * SQ * DM;

    split_all<<<dim3(4096, 7), 256>>>(query, key, value, Wq, Wk, Wv, Wo);

    const int SM_M0 = 1024 + 2 * (2 * 128 * 32 * 2 + 2 * 128 * 32 * 2);  // 66560
    const int SM_M1 = 1024 + 2 * (2 * 128 * 32 * 2 + 2 * 64 * 32 * 2);   // 50176
    const int SM_QK = 1024 + 2 * (128 * 64 * 2) + 2 * 2 * (128 * 64 * 2); // 99328
    cudaFuncSetAttribute(mm_bf<128, 0, 2>, cudaFuncAttributeMaxDynamicSharedMemorySize, SM_M0);
    cudaFuncSetAttribute(mm_bf<64, 1, 3>,  cudaFuncAttributeMaxDynamicSharedMemorySize, SM_M1);
    cudaFuncSetAttribute(qk64, cudaFuncAttributeMaxDynamicSharedMemorySize, SM_QK);

    // merged Q/K/V projections (z = 0,1,2)
    dim3 gqkv(8, 32, 3);
    mm_bf<128, 0, 2><<<gqkv, 256, SM_M0>>>(
        O_INH, O_INL, DM, 0, 4 * MI,
        O_WH, O_WL, DM, 0, 1 * MI,
        nullptr, O_QH, O_QL, DM, 0, 8 * MI,
        nullptr, 0, DM, 1.f, bq, bk, bv, 3);

    transpose_hl<<<dim3(DM / 32, SQ / 32, NB), dim3(32, 8)>>>();

    // QK^T: A loaded once, NT=4 B tiles per block; exp epilogue + partial sums
    qk64<<<dim3(16 / NT, 16, NB * NH), 256, SM_QK>>>(scores);

    // PV with fused normalization; P written back into scores
    dim3 gpv(1, 16, NB * NH);
    mm_bf<64, 1, 3><<<gpv, 256, SM_M1>>>(
        0, 0, SQ, 0, 0, O_VTH, O_VTL, SQ, (long)DM * SQ, (long)DK * SQ,
        nullptr, O_CH, O_CL, DM, (long)SQ * DM, DK,
        scores, (long)SQ * SQ, SQ, 1.f, nullptr, nullptr, nullptr, NH);

    // out = ctx @ Wo^T + bo
    dim3 gproj(8, 32, 1);
    mm_bf<128, 0, 2><<<gproj, 256, SM_M0>>>(
        O_CH, O_CL, DM, 0, 0, O_WH + 3 * MI, O_WL + 3 * MI, DM, 0, 0,
        out, 0, 0, DM, 0, 0, nullptr, 0, DM, 1.f, bo, nullptr, nullptr, 1);
}